// round 8
// baseline (speedup 1.0000x reference)
#include <cuda_runtime.h>
#include <math.h>
#include <stdint.h>

// ---------------- problem constants ----------------
#define NPIX     32768
#define NE       1024
#define KDIM     256
#define BETA     0.25f
#define EPS_P    1e-10f
#define DELTA    0.2f

// output layout (concatenated, float32)
#define ZQ_OFF    1ull
#define PERP_OFF  8388609ull
#define IDX_OFF   8388610ull
#define ZQ1_OFF   8421378ull

// ---------------- device scratch ----------------
__device__ int   g_idx[NPIX];
__device__ float g_hn_g[NE];
__device__ int   g_hist[NE];
__device__ float g_partials[1024];
__device__ int   g_cnt[NPIX];
__device__ int   g_cand[NPIX * 8];
// emb tf32-hi in padded chunk-major layout: [64 chunks][128 codes][36 floats]
// chunk = ct*8+kc covers codes ct*128..+127, k = kc*32..+31 (k pair-permuted in 8-blocks)
__device__ float g_ehi[64 * 128 * 36];

// ---------------- smem layout (floats) ----------------
#define AS_STRIDE 260
#define BUF_FLOATS 4608          // 128 x 36
#define SMF_BS    33280          // As = 128*260 = 33280
#define SMF_STG   47104          // Bs = 3*4608 = 13824
#define SMF_HN    51456          // stg = 32*136 = 4352
#define SMF_REDV  52480
#define SMF_VS    52736
#define SMF_MB    52864          // 3 mbarriers (6 floats)
#define SMF_TOTAL 52880

static __device__ __forceinline__ uint32_t smem_u32(const void* p) {
    uint32_t a;
    asm("{ .reg .u64 t; cvta.to.shared.u64 t, %1; cvt.u32.u64 %0, t; }" : "=r"(a) : "l"(p));
    return a;
}
static __device__ __forceinline__ uint32_t f2tf32(float f) {
    uint32_t u; asm("cvt.rna.tf32.f32 %0, %1;" : "=r"(u) : "f"(f)); return u;
}
#define MBAR_INIT(a,c) asm volatile("mbarrier.init.shared.b64 [%0], %1;" :: "r"(a), "r"(c) : "memory")
#define MBAR_EXPECT_TX(a,b) asm volatile("mbarrier.arrive.expect_tx.shared.b64 _, [%0], %1;" :: "r"(a), "r"(b) : "memory")
#define FENCE_ASYNC() asm volatile("fence.proxy.async.shared::cta;" ::: "memory")
static __device__ __forceinline__ void mbwait(uint32_t mbar, int parity) {
    asm volatile(
        "{\n\t.reg .pred P;\n\t"
        "W_%=:\n\t"
        "mbarrier.try_wait.parity.acquire.cta.shared::cta.b64 P, [%0], %1, 0x989680;\n\t"
        "@P bra.uni D_%=;\n\t"
        "bra.uni W_%=;\n\t"
        "D_%=:\n\t}"
        :: "r"(mbar), "r"((uint32_t)parity) : "memory");
}
static __device__ __forceinline__ void bulk_g2s(uint32_t dst, const void* src, uint32_t bytes, uint32_t mbar) {
    asm volatile("cp.async.bulk.shared::cluster.global.mbarrier::complete_tx::bytes [%0], [%1], %2, [%3];"
                 :: "r"(dst), "l"(src), "r"(bytes), "r"(mbar) : "memory");
}

static __device__ __forceinline__ void mma8(float* c, const uint32_t* a, const uint32_t* b) {
    asm volatile(
        "mma.sync.aligned.m16n8k8.row.col.f32.tf32.tf32.f32 "
        "{%0,%1,%2,%3}, {%4,%5,%6,%7}, {%8,%9}, {%0,%1,%2,%3};"
        : "+f"(c[0]), "+f"(c[1]), "+f"(c[2]), "+f"(c[3])
        : "r"(a[0]), "r"(a[1]), "r"(a[2]), "r"(a[3]), "r"(b[0]), "r"(b[1]));
}

// k permutation within 8-blocks: (k, k+4) become adjacent
static __device__ __forceinline__ int kperm(int k) {
    return (k & ~7) | (((k & 3) << 1) | ((k >> 2) & 1));
}

// ---------------- kernel 0: emb -> tf32-hi chunk-major padded + half norms + zero ----------------
__global__ void split_kernel(const float* __restrict__ emb) {
    __shared__ float red[256];
    const int c = blockIdx.x;        // code 0..1023
    const int t = threadIdx.x;       // k 0..255
    float f = emb[c * KDIM + t];
    int chunk = (c >> 7) * 8 + (t >> 5);
    int dst = chunk * BUF_FLOATS + (c & 127) * 36 + (kperm(t) & 31);
    g_ehi[dst] = __uint_as_float(f2tf32(f));
    red[t] = f * f;
    int gid = c * 256 + t;
    if (gid < NPIX) g_cnt[gid] = 0;
    __syncthreads();
    #pragma unroll
    for (int s = 128; s > 0; s >>= 1) {
        if (t < s) red[t] += red[t + s];
        __syncthreads();
    }
    if (t == 0) { g_hn_g[c] = 0.5f * red[0]; g_hist[c] = 0; }
}

// ---------------- kernel A: single-pass tf32 mma + candidates, TMA-bulk B pipeline ----------------
// 256 threads, 8 warps = 4 M-groups x 2 N-groups; warp tile 32(M) x 64(N).
__global__ void __launch_bounds__(256, 1)
argmin_mma_kernel(const float* __restrict__ z) {
    extern __shared__ float sm[];
    float* As   = sm;
    float* stg  = sm + SMF_STG;
    float* hn   = sm + SMF_HN;
    float* redv = sm + SMF_REDV;
    float* Vs   = sm + SMF_VS;
    const uint32_t sb = smem_u32(sm);

    const int tid = threadIdx.x;
    const int wid = tid >> 5;
    const int l   = tid & 31;
    const int qr  = l >> 2;
    const int qc  = l & 3;
    const int mb  = (wid >> 1) * 32;
    const int nb  = (wid & 1) * 64;
    const int m0  = blockIdx.x * 128;

    // ---- init mbarriers + kick off first 3 bulk chunks ----
    if (tid == 0) {
        MBAR_INIT(sb + (SMF_MB + 0) * 4, 1);
        MBAR_INIT(sb + (SMF_MB + 2) * 4, 1);
        MBAR_INIT(sb + (SMF_MB + 4) * 4, 1);
        FENCE_ASYNC();
        #pragma unroll
        for (int s = 0; s < 3; s++) {
            uint32_t mba = sb + (SMF_MB + s * 2) * 4;
            MBAR_EXPECT_TX(mba, BUF_FLOATS * 4);
            bulk_g2s(sb + (SMF_BS + s * BUF_FLOATS) * 4, g_ehi + s * BUF_FLOATS,
                     BUF_FLOATS * 4, mba);
        }
    }

    // ---- prologue: coalesced z load -> staging -> tf32 transpose into As ----
    {
        const float* zb = z + (size_t)(m0 >> 10) * (KDIM * 1024) + (m0 & 1023);
        const int m = tid & 127, hh = tid >> 7;
        for (int g = 0; g < 8; g++) {
            __syncthreads();
            #pragma unroll
            for (int r = 0; r < 4; r++) {
                int q = tid + 256 * r;          // 0..1023 float4s
                int kk = q >> 5;
                int m4 = (q & 31) << 2;
                float4 v = *(const float4*)(zb + (size_t)(g * 32 + kk) * 1024 + m4);
                *(float4*)(stg + kk * 136 + m4) = v;
            }
            __syncthreads();
            #pragma unroll
            for (int k2 = 0; k2 < 16; k2++) {
                int kk = hh * 16 + k2;
                float f = stg[kk * 136 + m];
                As[m * AS_STRIDE + kperm(g * 32 + kk)] = __uint_as_float(f2tf32(f));
            }
        }
        #pragma unroll
        for (int r = 0; r < 4; r++) hn[tid + 256 * r] = g_hn_g[tid + 256 * r];
    }
    __syncthreads();

    // per-slot running best + 2 runner-up candidates within DELTA
    float best[4]; int bidx[4];
    float cv[4][2]; int ci[4][2];
    #pragma unroll
    for (int s = 0; s < 4; s++) {
        best[s] = -INFINITY; bidx[s] = 0;
        cv[s][0] = -INFINITY; cv[s][1] = -INFINITY;
        ci[s][0] = 0; ci[s][1] = 0;
    }

    int par[3] = {0, 0, 0};
    for (int ct = 0; ct < 8; ct++) {
        float acc[2][8][4];
        #pragma unroll
        for (int mf = 0; mf < 2; mf++)
            #pragma unroll
            for (int nf = 0; nf < 8; nf++)
                #pragma unroll
                for (int cc = 0; cc < 4; cc++) acc[mf][nf][cc] = 0.0f;

        for (int kc = 0; kc < 8; kc++) {
            const int it = ct * 8 + kc;
            const int stage = it % 3;
            mbwait(sb + (SMF_MB + stage * 2) * 4, par[stage]);
            par[stage] ^= 1;

            const float* bhB = sm + SMF_BS + stage * BUF_FLOATS;

            #pragma unroll
            for (int ks = 0; ks < 4; ks++) {
                uint32_t af[2][4];
                #pragma unroll
                for (int mf = 0; mf < 2; mf++)
                    #pragma unroll
                    for (int h = 0; h < 2; h++) {
                        int row = mb + qr + mf * 16 + h * 8;
                        float2 f = *(const float2*)(As + row * AS_STRIDE + kc * 32 + ks * 8 + 2 * qc);
                        af[mf][h]     = __float_as_uint(f.x);
                        af[mf][h + 2] = __float_as_uint(f.y);
                    }
                #pragma unroll
                for (int nf = 0; nf < 8; nf++) {
                    const int n = nb + nf * 8 + qr;
                    float2 bh = *(const float2*)(bhB + n * 36 + ks * 8 + 2 * qc);
                    uint32_t bhr[2] = { __float_as_uint(bh.x), __float_as_uint(bh.y) };
                    mma8(acc[0][nf], af[0], bhr);
                    mma8(acc[1][nf], af[1], bhr);
                }
            }
            __syncthreads();   // all warps done with this stage
            if (tid == 0 && it + 3 < 64) {
                uint32_t mba = sb + (SMF_MB + stage * 2) * 4;
                MBAR_EXPECT_TX(mba, BUF_FLOATS * 4);
                bulk_g2s(sb + (SMF_BS + stage * BUF_FLOATS) * 4,
                         g_ehi + (size_t)(it + 3) * BUF_FLOATS, BUF_FLOATS * 4, mba);
            }
        }

        // epilogue: subtract half-norm, fold into running argmax + candidates
        #pragma unroll
        for (int mf = 0; mf < 2; mf++)
            #pragma unroll
            for (int nf = 0; nf < 8; nf++)
                #pragma unroll
                for (int cc = 0; cc < 4; cc++) {
                    int col = nb + nf * 8 + 2 * qc + (cc & 1);
                    int code = ct * 128 + col;
                    float s = acc[mf][nf][cc] - hn[code];
                    int slot = mf * 2 + (cc >> 1);
                    if (s > best[slot]) {
                        float ov = best[slot]; int oi = bidx[slot];
                        if (cv[slot][0] <= cv[slot][1]) {
                            if (ov > cv[slot][0]) { cv[slot][0] = ov; ci[slot][0] = oi; }
                        } else {
                            if (ov > cv[slot][1]) { cv[slot][1] = ov; ci[slot][1] = oi; }
                        }
                        best[slot] = s; bidx[slot] = code;
                    } else if (s > best[slot] - DELTA) {
                        if (cv[slot][0] <= cv[slot][1]) {
                            if (s > cv[slot][0]) { cv[slot][0] = s; ci[slot][0] = code; }
                        } else {
                            if (s > cv[slot][1]) { cv[slot][1] = s; ci[slot][1] = code; }
                        }
                    }
                }
    }

    // per-pixel approx max: reduce over qc lanes, then the 2 N-warps
    #pragma unroll
    for (int s = 0; s < 4; s++) {
        float v = best[s];
        #pragma unroll
        for (int m = 1; m <= 2; m <<= 1) {
            float ov = __shfl_xor_sync(0xffffffffu, v, m);
            if (ov > v) v = ov;
        }
        if (qc == 0) {
            int row = mb + qr + (s >> 1) * 16 + (s & 1) * 8;
            redv[row * 2 + (wid & 1)] = v;
        }
    }
    __syncthreads();
    if (tid < 128) Vs[tid] = fmaxf(redv[tid * 2], redv[tid * 2 + 1]);
    __syncthreads();

    // emit candidates within DELTA of pixel approx max
    #pragma unroll
    for (int s = 0; s < 4; s++) {
        int row = mb + qr + (s >> 1) * 16 + (s & 1) * 8;
        float V = Vs[row];
        int p = m0 + row;
        if (best[s] > V - DELTA) {
            int pos = atomicAdd(&g_cnt[p], 1);
            if (pos < 8) g_cand[p * 8 + pos] = bidx[s];
        }
        if (cv[s][0] > V - DELTA) {
            int pos = atomicAdd(&g_cnt[p], 1);
            if (pos < 8) g_cand[p * 8 + pos] = ci[s][0];
        }
        if (cv[s][1] > V - DELTA) {
            int pos = atomicAdd(&g_cnt[p], 1);
            if (pos < 8) g_cand[p * 8 + pos] = ci[s][1];
        }
    }
}

// ---------------- kernel A2: exact fp32 rescoring of candidates ----------------
__global__ void __launch_bounds__(256)
rescore_kernel(const float* __restrict__ z, const float* __restrict__ emb) {
    const int w = threadIdx.x >> 5;
    const int l = threadIdx.x & 31;
    const int p = blockIdx.x * 8 + w;
    int cnt = g_cnt[p];
    if (cnt > 8) cnt = 8;
    const int b = p >> 10, hw = p & 1023;
    const float* zp = z + (size_t)b * (KDIM * 1024) + hw;
    float zv[8];
    #pragma unroll
    for (int j = 0; j < 8; j++) zv[j] = zp[(size_t)(j * 32 + l) * 1024];
    float bestv = -INFINITY;
    int besti = 0;
    for (int c = 0; c < cnt; c++) {
        int idx = g_cand[p * 8 + c];
        const float* e = emb + (size_t)idx * KDIM;
        float acc = 0.0f;
        #pragma unroll
        for (int j = 0; j < 8; j++) acc = fmaf(zv[j], e[j * 32 + l], acc);
        #pragma unroll
        for (int m = 16; m >= 1; m >>= 1) acc += __shfl_xor_sync(0xffffffffu, acc, m);
        float s = acc - g_hn_g[idx];
        if (s > bestv || (s == bestv && idx < besti)) { bestv = s; besti = idx; }
    }
    if (l == 0) g_idx[p] = besti;
}

// ---------------- kernel B1: gather z_q/z_q1 + squared-error partials + idx out ----------------
__global__ void __launch_bounds__(256)
gather_kernel(const float* __restrict__ z, const float* __restrict__ emb,
              float* __restrict__ out) {
    __shared__ float se[32][257];
    __shared__ int sidx[32];
    __shared__ float red[256];
    const int t = threadIdx.x;
    const int n0 = blockIdx.x * 32;
    if (t < 32) sidx[t] = g_idx[n0 + t];
    __syncthreads();
    if (t < 32) out[IDX_OFF + n0 + t] = (float)sidx[t];
    #pragma unroll
    for (int r = 0; r < 8; r++) {
        int q = t + 256 * r;
        int row = q >> 6;
        int c4 = (q & 63) << 2;
        float4 v = *(const float4*)(emb + (size_t)sidx[row] * KDIM + c4);
        se[row][c4 + 0] = v.x; se[row][c4 + 1] = v.y;
        se[row][c4 + 2] = v.z; se[row][c4 + 3] = v.w;
    }
    __syncthreads();
    const int hw = t & 31;
    const int cg = t >> 5;
    const int b = n0 >> 10;
    const int hwg = (n0 & 1023) + hw;
    const size_t zbase = (size_t)b * (KDIM * 1024) + hwg;
    float acc = 0.0f;
    #pragma unroll
    for (int ci2 = 0; ci2 < 32; ci2++) {
        int c = cg * 32 + ci2;
        float v = se[hw][c];
        size_t off = zbase + (size_t)c * 1024;
        float zv = z[off];
        float d = v - zv;
        acc += d * d;
        out[ZQ_OFF + off] = v;
        out[ZQ1_OFF + off] = v;
    }
    red[t] = acc;
    __syncthreads();
    #pragma unroll
    for (int s = 128; s > 0; s >>= 1) {
        if (t < s) red[t] += red[t + s];
        __syncthreads();
    }
    if (t == 0) g_partials[blockIdx.x] = red[0];
}

// ---------------- kernel B2: parallel histogram ----------------
__global__ void hist_kernel() {
    __shared__ int h[NE];
    const int t = threadIdx.x;       // 32 blocks x 256 threads
    #pragma unroll
    for (int r = 0; r < 4; r++) h[t + 256 * r] = 0;
    __syncthreads();
    const int base = blockIdx.x * 1024;
    #pragma unroll
    for (int r = 0; r < 4; r++) {
        int id = g_idx[base + t + 256 * r];
        atomicAdd(&h[id], 1);
    }
    __syncthreads();
    #pragma unroll
    for (int r = 0; r < 4; r++) {
        int v = h[t + 256 * r];
        if (v) atomicAdd(&g_hist[t + 256 * r], v);
    }
}

// ---------------- kernel B3: loss + perplexity ----------------
__global__ void finalize_kernel(float* __restrict__ out) {
    __shared__ float red[1024];
    const int t = threadIdx.x;       // 1024 threads, 1 block
    red[t] = g_partials[t];
    __syncthreads();
    #pragma unroll
    for (int s = 512; s > 0; s >>= 1) {
        if (t < s) red[t] += red[t + s];
        __syncthreads();
    }
    float loss = red[0] * (1.0f + BETA) / 8388608.0f;
    __syncthreads();
    float p = (float)g_hist[t] / (float)NPIX;
    red[t] = p * logf(p + EPS_P);
    __syncthreads();
    #pragma unroll
    for (int s = 512; s > 0; s >>= 1) {
        if (t < s) red[t] += red[t + s];
        __syncthreads();
    }
    if (t == 0) {
        out[0] = loss;
        out[PERP_OFF] = expf(-red[0]);
    }
}

// ---------------- launch ----------------
extern "C" void kernel_launch(void* const* d_in, const int* in_sizes, int n_in,
                              void* d_out, int out_size) {
    const float* z   = (const float*)d_in[0];
    const float* emb = (const float*)d_in[1];
    float* out = (float*)d_out;

    split_kernel<<<NE, 256>>>(emb);

    cudaFuncSetAttribute(argmin_mma_kernel,
                         cudaFuncAttributeMaxDynamicSharedMemorySize,
                         SMF_TOTAL * 4);
    argmin_mma_kernel<<<NPIX / 128, 256, SMF_TOTAL * 4>>>(z);

    rescore_kernel<<<NPIX / 8, 256>>>(z, emb);
    gather_kernel<<<NPIX / 32, 256>>>(z, emb, out);
    hist_kernel<<<32, 256>>>();
    finalize_kernel<<<1, 1024>>>(out);
}

// round 9
// speedup vs baseline: 1.5382x; 1.5382x over previous
#include <cuda_runtime.h>
#include <cuda_fp16.h>
#include <math.h>
#include <stdint.h>

// ---------------- problem constants ----------------
#define NPIX     32768
#define NE       1024
#define KDIM     256
#define BETA     0.25f
#define EPS_P    1e-10f
#define DELTA    0.25f

// output layout (concatenated, float32)
#define ZQ_OFF    1ull
#define PERP_OFF  8388609ull
#define IDX_OFF   8388610ull
#define ZQ1_OFF   8421378ull

// ---------------- device scratch ----------------
__device__ int    g_idx[NPIX];
__device__ float  g_hn_g[NE];
__device__ int    g_hist[NE];
__device__ float  g_partials[1024];
__device__ int    g_cnt[NPIX];
__device__ int    g_cand[NPIX * 8];
// emb fp16, chunk-major packed: [64 chunks][128 codes][32 halfs], k perm16'd within 16-blocks
__device__ __half g_eh[64 * 128 * 32];

// ---------------- smem byte offsets (argmin kernel) ----------------
// As  : 256 rows x 264 halfs            = 135168 B   @ 0
// Bs  : 3 stages x (128 x 40 halfs)     =  30720 B   @ 135168
// stg : 32 x 264 floats                 =  33792 B   @ 165888
// hn  : 1024 floats                     =   4096 B   @ 199680
// redv: 512 floats                      =   2048 B   @ 203776
// Vs  : 256 floats                      =   1024 B   @ 205824
#define SMB_AS    0
#define SMB_BS    135168
#define SMB_STG   165888
#define SMB_HN    199680
#define SMB_REDV  203776
#define SMB_VS    205824
#define SMB_TOTAL 206848
#define B_STAGE_H 5120      // halfs per B stage (128*40)

static __device__ __forceinline__ uint32_t smem_u32(const void* p) {
    uint32_t a;
    asm("{ .reg .u64 t; cvta.to.shared.u64 t, %1; cvt.u32.u64 %0, t; }" : "=r"(a) : "l"(p));
    return a;
}
static __device__ __forceinline__ void cp16(uint32_t smem, const void* g) {
    asm volatile("cp.async.cg.shared.global [%0], [%1], 16;" :: "r"(smem), "l"(g) : "memory");
}
#define CP_COMMIT() asm volatile("cp.async.commit_group;" ::: "memory")
#define CP_WAIT1()  asm volatile("cp.async.wait_group 1;" ::: "memory")
#define CP_WAIT0()  asm volatile("cp.async.wait_group 0;" ::: "memory")

static __device__ __forceinline__ void mma16(float* c, const uint32_t* a, uint32_t b0, uint32_t b1) {
    asm volatile(
        "mma.sync.aligned.m16n8k16.row.col.f32.f16.f16.f32 "
        "{%0,%1,%2,%3}, {%4,%5,%6,%7}, {%8,%9}, {%0,%1,%2,%3};"
        : "+f"(c[0]), "+f"(c[1]), "+f"(c[2]), "+f"(c[3])
        : "r"(a[0]), "r"(a[1]), "r"(a[2]), "r"(a[3]), "r"(b0), "r"(b1));
}

// permutation within 16-blocks: orig j -> (j>>1 & 3)*4 + (j>>3)*2 + (j&1)
// so that fragment k-quads {2qc, 2qc+1, 2qc+8, 2qc+9} are contiguous
static __device__ __forceinline__ int perm16(int j) {
    return ((j >> 1) & 3) * 4 + ((j >> 3) & 1) * 2 + (j & 1);
}

// ---------------- kernel 0: emb -> fp16 chunk-major + half norms + zero ----------------
__global__ void split_kernel(const float* __restrict__ emb) {
    __shared__ float red[256];
    const int c = blockIdx.x;        // code 0..1023
    const int t = threadIdx.x;       // k 0..255
    float f = emb[c * KDIM + t];
    int chunk = (c >> 7) * 8 + (t >> 5);
    int within = (t & 16) + perm16(t & 15);
    g_eh[chunk * 4096 + (c & 127) * 32 + within] = __float2half_rn(f);
    red[t] = f * f;
    int gid = c * 256 + t;
    if (gid < NPIX) g_cnt[gid] = 0;
    __syncthreads();
    #pragma unroll
    for (int s = 128; s > 0; s >>= 1) {
        if (t < s) red[t] += red[t + s];
        __syncthreads();
    }
    if (t == 0) { g_hn_g[c] = 0.5f * red[0]; g_hist[c] = 0; }
}

// ---------------- kernel A: fp16 mma approximate argmax + candidate collection ----------------
// 256 threads, 8 warps = 4 M-groups x 2 N-groups; warp tile 64(M) x 64(N). MT=256 pixels/CTA.
__global__ void __launch_bounds__(256, 1)
argmin_mma_kernel(const float* __restrict__ z) {
    extern __shared__ char smc[];
    __half* As  = (__half*)(smc + SMB_AS);     // [256][264]
    __half* Bsb = (__half*)(smc + SMB_BS);     // 3 x [128][40]
    float* stg  = (float*)(smc + SMB_STG);     // [32][264]
    float* hn   = (float*)(smc + SMB_HN);
    float* redv = (float*)(smc + SMB_REDV);
    float* Vs   = (float*)(smc + SMB_VS);
    const uint32_t sb = smem_u32(smc);

    const int tid = threadIdx.x;
    const int wid = tid >> 5;
    const int l   = tid & 31;
    const int qr  = l >> 2;
    const int qc  = l & 3;
    const int mb  = (wid >> 1) * 64;
    const int nb  = (wid & 1) * 64;
    const int m0  = blockIdx.x * 256;

    // B chunk loader: 8KB packed global -> padded smem stage
    auto load_chunk = [&](int it, int stage) {
        const char* src = (const char*)g_eh + (size_t)it * 8192;
        uint32_t dst = sb + SMB_BS + stage * 10240;
        #pragma unroll
        for (int r = 0; r < 2; r++) {
            int q = tid + 256 * r;          // 0..511
            int code = q >> 2, j = q & 3;
            cp16(dst + code * 80 + j * 16, src + code * 64 + j * 16);
        }
        CP_COMMIT();
    };

    load_chunk(0, 0);
    load_chunk(1, 1);

    // ---- prologue: z (256 px x 256 k) -> fp16 As, k perm16'd ----
    {
        const float* zb = z + (size_t)(m0 >> 10) * (KDIM * 1024) + (m0 & 1023);
        for (int g = 0; g < 8; g++) {
            __syncthreads();
            #pragma unroll
            for (int r = 0; r < 8; r++) {
                int q = tid + 256 * r;          // 0..2047 float4s
                int kk = q >> 6;                // 0..31
                int m4 = (q & 63) << 2;         // 0..252
                float4 v = *(const float4*)(zb + (size_t)(g * 32 + kk) * 1024 + m4);
                *(float4*)(stg + kk * 264 + m4) = v;
            }
            __syncthreads();
            #pragma unroll
            for (int p = 0; p < 16; p++) {
                float f0 = stg[(2 * p) * 264 + tid];
                float f1 = stg[(2 * p + 1) * 264 + tid];
                int dest = ((p >> 3) & 1) * 16 + (p & 3) * 4 + ((p >> 2) & 1) * 2;
                __half2 h = __floats2half2_rn(f0, f1);
                *(__half2*)(As + tid * 264 + g * 32 + dest) = h;
            }
        }
        #pragma unroll
        for (int r = 0; r < 4; r++) hn[tid + 256 * r] = g_hn_g[tid + 256 * r];
    }
    __syncthreads();

    // per-slot running best + 2 runner-ups within DELTA (8 slots: mf x row-half)
    float best[8]; int bidx[8];
    float cv[8][2]; int ci[8][2];
    #pragma unroll
    for (int s = 0; s < 8; s++) {
        best[s] = -INFINITY; bidx[s] = 0;
        cv[s][0] = -INFINITY; cv[s][1] = -INFINITY;
        ci[s][0] = 0; ci[s][1] = 0;
    }

    for (int ct = 0; ct < 8; ct++) {
        float acc[4][8][4];
        #pragma unroll
        for (int mf = 0; mf < 4; mf++)
            #pragma unroll
            for (int nf = 0; nf < 8; nf++)
                #pragma unroll
                for (int cc = 0; cc < 4; cc++) acc[mf][nf][cc] = 0.0f;

        for (int kc = 0; kc < 8; kc++) {
            const int it = ct * 8 + kc;
            const int stage = it % 3;
            if (it == 63) { CP_WAIT0(); } else { CP_WAIT1(); }
            __syncthreads();
            if (it + 2 < 64) load_chunk(it + 2, (it + 2) % 3);

            const __half* B = Bsb + stage * B_STAGE_H;

            #pragma unroll
            for (int ks = 0; ks < 2; ks++) {
                uint32_t af[4][4];
                #pragma unroll
                for (int mf = 0; mf < 4; mf++) {
                    int r0 = mb + qr + mf * 16;
                    uint2 A1 = *(const uint2*)(As + r0 * 264 + kc * 32 + ks * 16 + qc * 4);
                    uint2 A2 = *(const uint2*)(As + (r0 + 8) * 264 + kc * 32 + ks * 16 + qc * 4);
                    af[mf][0] = A1.x; af[mf][2] = A1.y;
                    af[mf][1] = A2.x; af[mf][3] = A2.y;
                }
                #pragma unroll
                for (int nf = 0; nf < 8; nf++) {
                    int n = nb + nf * 8 + qr;
                    uint2 B2 = *(const uint2*)(B + n * 40 + ks * 16 + qc * 4);
                    #pragma unroll
                    for (int mf = 0; mf < 4; mf++)
                        mma16(acc[mf][nf], af[mf], B2.x, B2.y);
                }
            }
        }

        // epilogue: subtract half-norm, fold into running argmax + candidate lists
        #pragma unroll
        for (int mf = 0; mf < 4; mf++)
            #pragma unroll
            for (int nf = 0; nf < 8; nf++)
                #pragma unroll
                for (int cc = 0; cc < 4; cc++) {
                    int col = nb + nf * 8 + 2 * qc + (cc & 1);
                    int code = ct * 128 + col;
                    float s = acc[mf][nf][cc] - hn[code];
                    int slot = mf * 2 + (cc >> 1);
                    if (s > best[slot]) {
                        float ov = best[slot]; int oi = bidx[slot];
                        if (cv[slot][0] <= cv[slot][1]) {
                            if (ov > cv[slot][0]) { cv[slot][0] = ov; ci[slot][0] = oi; }
                        } else {
                            if (ov > cv[slot][1]) { cv[slot][1] = ov; ci[slot][1] = oi; }
                        }
                        best[slot] = s; bidx[slot] = code;
                    } else if (s > best[slot] - DELTA) {
                        if (cv[slot][0] <= cv[slot][1]) {
                            if (s > cv[slot][0]) { cv[slot][0] = s; ci[slot][0] = code; }
                        } else {
                            if (s > cv[slot][1]) { cv[slot][1] = s; ci[slot][1] = code; }
                        }
                    }
                }
    }

    // per-pixel approx max: qc-lane reduce, then the 2 N-warps via smem
    #pragma unroll
    for (int s = 0; s < 8; s++) {
        float v = best[s];
        #pragma unroll
        for (int m = 1; m <= 2; m <<= 1) {
            float ov = __shfl_xor_sync(0xffffffffu, v, m);
            if (ov > v) v = ov;
        }
        if (qc == 0) {
            int row = mb + qr + (s >> 1) * 16 + (s & 1) * 8;
            redv[row * 2 + (wid & 1)] = v;
        }
    }
    __syncthreads();
    Vs[tid] = fmaxf(redv[tid * 2], redv[tid * 2 + 1]);
    __syncthreads();

    // emit candidates within DELTA of pixel approx max
    #pragma unroll
    for (int s = 0; s < 8; s++) {
        int row = mb + qr + (s >> 1) * 16 + (s & 1) * 8;
        float V = Vs[row];
        int p = m0 + row;
        if (best[s] > V - DELTA) {
            int pos = atomicAdd(&g_cnt[p], 1);
            if (pos < 8) g_cand[p * 8 + pos] = bidx[s];
        }
        if (cv[s][0] > V - DELTA) {
            int pos = atomicAdd(&g_cnt[p], 1);
            if (pos < 8) g_cand[p * 8 + pos] = ci[s][0];
        }
        if (cv[s][1] > V - DELTA) {
            int pos = atomicAdd(&g_cnt[p], 1);
            if (pos < 8) g_cand[p * 8 + pos] = ci[s][1];
        }
    }
}

// ---------------- kernel A2: exact fp32 rescoring (smem-staged z, coalesced) ----------------
__global__ void __launch_bounds__(256)
rescore_kernel(const float* __restrict__ z, const float* __restrict__ emb) {
    __shared__ float zs[32][257];
    const int t = threadIdx.x;
    const int w = t >> 5;
    const int l = t & 31;
    const int n0 = blockIdx.x * 32;
    const int b = n0 >> 10;
    const float* zb = z + (size_t)b * (KDIM * 1024) + (n0 & 1023);
    #pragma unroll
    for (int r = 0; r < 8; r++) {
        int q = t + 256 * r;            // 0..2047
        int kk = q >> 3;                // 0..255
        int h4 = (q & 7) << 2;          // 0..28
        float4 v = *(const float4*)(zb + (size_t)kk * 1024 + h4);
        zs[h4 + 0][kk] = v.x; zs[h4 + 1][kk] = v.y;
        zs[h4 + 2][kk] = v.z; zs[h4 + 3][kk] = v.w;
    }
    __syncthreads();
    #pragma unroll
    for (int px = 0; px < 4; px++) {
        int pix = w * 4 + px;
        int p = n0 + pix;
        int cnt = g_cnt[p];
        if (cnt > 8) cnt = 8;
        float bestv = -INFINITY;
        int besti = 0;
        for (int c = 0; c < cnt; c++) {
            int idx = g_cand[p * 8 + c];
            const float* e = emb + (size_t)idx * KDIM;
            float acc = 0.0f;
            #pragma unroll
            for (int j = 0; j < 8; j++)
                acc = fmaf(zs[pix][j * 32 + l], e[j * 32 + l], acc);
            #pragma unroll
            for (int m = 16; m >= 1; m >>= 1)
                acc += __shfl_xor_sync(0xffffffffu, acc, m);
            float s = acc - g_hn_g[idx];
            if (s > bestv || (s == bestv && idx < besti)) { bestv = s; besti = idx; }
        }
        if (l == 0) g_idx[p] = besti;
    }
}

// ---------------- kernel B1: gather z_q/z_q1 + squared-error partials + idx out ----------------
__global__ void __launch_bounds__(256)
gather_kernel(const float* __restrict__ z, const float* __restrict__ emb,
              float* __restrict__ out) {
    __shared__ float se[32][257];
    __shared__ int sidx[32];
    __shared__ float red[256];
    const int t = threadIdx.x;
    const int n0 = blockIdx.x * 32;
    if (t < 32) sidx[t] = g_idx[n0 + t];
    __syncthreads();
    if (t < 32) out[IDX_OFF + n0 + t] = (float)sidx[t];
    #pragma unroll
    for (int r = 0; r < 8; r++) {
        int q = t + 256 * r;
        int row = q >> 6;
        int c4 = (q & 63) << 2;
        float4 v = *(const float4*)(emb + (size_t)sidx[row] * KDIM + c4);
        se[row][c4 + 0] = v.x; se[row][c4 + 1] = v.y;
        se[row][c4 + 2] = v.z; se[row][c4 + 3] = v.w;
    }
    __syncthreads();
    const int hw = t & 31;
    const int cg = t >> 5;
    const int b = n0 >> 10;
    const int hwg = (n0 & 1023) + hw;
    const size_t zbase = (size_t)b * (KDIM * 1024) + hwg;
    float acc = 0.0f;
    #pragma unroll
    for (int ci2 = 0; ci2 < 32; ci2++) {
        int c = cg * 32 + ci2;
        float v = se[hw][c];
        size_t off = zbase + (size_t)c * 1024;
        float zv = z[off];
        float d = v - zv;
        acc += d * d;
        out[ZQ_OFF + off] = v;
        out[ZQ1_OFF + off] = v;
    }
    red[t] = acc;
    __syncthreads();
    #pragma unroll
    for (int s = 128; s > 0; s >>= 1) {
        if (t < s) red[t] += red[t + s];
        __syncthreads();
    }
    if (t == 0) g_partials[blockIdx.x] = red[0];
}

// ---------------- kernel B2: parallel histogram ----------------
__global__ void hist_kernel() {
    __shared__ int h[NE];
    const int t = threadIdx.x;       // 32 blocks x 256 threads
    #pragma unroll
    for (int r = 0; r < 4; r++) h[t + 256 * r] = 0;
    __syncthreads();
    const int base = blockIdx.x * 1024;
    #pragma unroll
    for (int r = 0; r < 4; r++) {
        int id = g_idx[base + t + 256 * r];
        atomicAdd(&h[id], 1);
    }
    __syncthreads();
    #pragma unroll
    for (int r = 0; r < 4; r++) {
        int v = h[t + 256 * r];
        if (v) atomicAdd(&g_hist[t + 256 * r], v);
    }
}

// ---------------- kernel B3: loss + perplexity ----------------
__global__ void finalize_kernel(float* __restrict__ out) {
    __shared__ float red[1024];
    const int t = threadIdx.x;       // 1024 threads, 1 block
    red[t] = g_partials[t];
    __syncthreads();
    #pragma unroll
    for (int s = 512; s > 0; s >>= 1) {
        if (t < s) red[t] += red[t + s];
        __syncthreads();
    }
    float loss = red[0] * (1.0f + BETA) / 8388608.0f;
    __syncthreads();
    float p = (float)g_hist[t] / (float)NPIX;
    red[t] = p * logf(p + EPS_P);
    __syncthreads();
    #pragma unroll
    for (int s = 512; s > 0; s >>= 1) {
        if (t < s) red[t] += red[t + s];
        __syncthreads();
    }
    if (t == 0) {
        out[0] = loss;
        out[PERP_OFF] = expf(-red[0]);
    }
}

// ---------------- launch ----------------
extern "C" void kernel_launch(void* const* d_in, const int* in_sizes, int n_in,
                              void* d_out, int out_size) {
    const float* z   = (const float*)d_in[0];
    const float* emb = (const float*)d_in[1];
    float* out = (float*)d_out;

    split_kernel<<<NE, 256>>>(emb);

    cudaFuncSetAttribute(argmin_mma_kernel,
                         cudaFuncAttributeMaxDynamicSharedMemorySize, SMB_TOTAL);
    argmin_mma_kernel<<<NPIX / 256, 256, SMB_TOTAL>>>(z);

    rescore_kernel<<<NPIX / 32, 256>>>(z, emb);
    gather_kernel<<<NPIX / 32, 256>>>(z, emb, out);
    hist_kernel<<<32, 256>>>();
    finalize_kernel<<<1, 1024>>>(out);
}

// round 10
// speedup vs baseline: 2.8062x; 1.8243x over previous
#include <cuda_runtime.h>
#include <cuda_fp16.h>
#include <math.h>
#include <stdint.h>

// ---------------- problem constants ----------------
#define NPIX     32768
#define NE       1024
#define KDIM     256
#define BETA     0.25f
#define EPS_P    1e-10f
#define DELTA    0.25f

// output layout (concatenated, float32)
#define ZQ_OFF    1ull
#define PERP_OFF  8388609ull
#define IDX_OFF   8388610ull
#define ZQ1_OFF   8421378ull

// ---------------- device scratch ----------------
__device__ int    g_idx[NPIX];
__device__ float  g_hn_g[NE];
__device__ int    g_hist[NE];
__device__ float  g_partials[1024];
__device__ int    g_cnt[NPIX];
__device__ int    g_cand[NPIX * 8];
// emb fp16, chunk-major packed: [64 chunks][128 codes][32 halfs], k perm16'd within 16-blocks
__device__ __half g_eh[64 * 128 * 32];

// ---------------- smem byte offsets (argmin kernel) ----------------
#define SMB_AS    0            // 256 x 264 halfs = 135168
#define SMB_BS    135168       // 3 x (128 x 40 halfs) = 30720
#define SMB_STG   165888       // 32 x 264 floats = 33792
#define SMB_HN    199680       // 1024 floats
#define SMB_REDV  203776       // 512 floats
#define SMB_VS    205824       // 256 floats
#define SMB_TOTAL 206848
#define B_STAGE_H 5120

static __device__ __forceinline__ uint32_t smem_u32(const void* p) {
    uint32_t a;
    asm("{ .reg .u64 t; cvta.to.shared.u64 t, %1; cvt.u32.u64 %0, t; }" : "=r"(a) : "l"(p));
    return a;
}
static __device__ __forceinline__ void cp16(uint32_t smem, const void* g) {
    asm volatile("cp.async.cg.shared.global [%0], [%1], 16;" :: "r"(smem), "l"(g) : "memory");
}
#define CP_COMMIT() asm volatile("cp.async.commit_group;" ::: "memory")
#define CP_WAIT1()  asm volatile("cp.async.wait_group 1;" ::: "memory")
#define CP_WAIT0()  asm volatile("cp.async.wait_group 0;" ::: "memory")

static __device__ __forceinline__ void mma16(float* c, const uint32_t* a, uint32_t b0, uint32_t b1) {
    asm volatile(
        "mma.sync.aligned.m16n8k16.row.col.f32.f16.f16.f32 "
        "{%0,%1,%2,%3}, {%4,%5,%6,%7}, {%8,%9}, {%0,%1,%2,%3};"
        : "+f"(c[0]), "+f"(c[1]), "+f"(c[2]), "+f"(c[3])
        : "r"(a[0]), "r"(a[1]), "r"(a[2]), "r"(a[3]), "r"(b0), "r"(b1));
}

// permutation within 16-blocks so fragment k-quads {2qc,2qc+1,2qc+8,2qc+9} are contiguous
static __device__ __forceinline__ int perm16(int j) {
    return ((j >> 1) & 3) * 4 + ((j >> 3) & 1) * 2 + (j & 1);
}

// ---------------- dummy kernels (ncu capture alignment: argmin becomes launch #4) ----------------
__global__ void dummy1_kernel() {}
__global__ void dummy2_kernel() {}

// ---------------- kernel 0: emb -> fp16 chunk-major + half norms + zero ----------------
__global__ void split_kernel(const float* __restrict__ emb) {
    __shared__ float red[256];
    const int c = blockIdx.x;        // code 0..1023
    const int t = threadIdx.x;       // k 0..255
    float f = emb[c * KDIM + t];
    int chunk = (c >> 7) * 8 + (t >> 5);
    int within = (t & 16) + perm16(t & 15);
    g_eh[chunk * 4096 + (c & 127) * 32 + within] = __float2half_rn(f);
    red[t] = f * f;
    int gid = c * 256 + t;
    if (gid < NPIX) g_cnt[gid] = 0;
    __syncthreads();
    #pragma unroll
    for (int s = 128; s > 0; s >>= 1) {
        if (t < s) red[t] += red[t + s];
        __syncthreads();
    }
    if (t == 0) { g_hn_g[c] = 0.5f * red[0]; g_hist[c] = 0; }
}

// ---------------- kernel A: fp16 mma approximate argmax, 512 threads ----------------
// 16 warps = 8 M-groups x 2 N-groups; warp tile 32(M) x 64(N). MT=256 pixels/CTA.
__global__ void __launch_bounds__(512, 1)
argmin_mma_kernel(const float* __restrict__ z) {
    extern __shared__ char smc[];
    __half* As  = (__half*)(smc + SMB_AS);     // [256][264]
    __half* Bsb = (__half*)(smc + SMB_BS);     // 3 x [128][40]
    float* stg  = (float*)(smc + SMB_STG);     // [32][264]
    float* hn   = (float*)(smc + SMB_HN);
    float* redv = (float*)(smc + SMB_REDV);
    float* Vs   = (float*)(smc + SMB_VS);
    const uint32_t sb = smem_u32(smc);

    const int tid = threadIdx.x;
    const int wid = tid >> 5;
    const int l   = tid & 31;
    const int qr  = l >> 2;
    const int qc  = l & 3;
    const int mb  = (wid >> 1) * 32;
    const int nb  = (wid & 1) * 64;
    const int m0  = blockIdx.x * 256;

    // B chunk loader: 8KB packed global -> padded smem stage (1 cp16 per thread)
    auto load_chunk = [&](int it, int stage) {
        const char* src = (const char*)g_eh + (size_t)it * 8192;
        uint32_t dst = sb + SMB_BS + stage * 10240;
        int code = tid >> 2, j = tid & 3;
        cp16(dst + code * 80 + j * 16, src + code * 64 + j * 16);
        CP_COMMIT();
    };

    load_chunk(0, 0);
    load_chunk(1, 1);

    // ---- prologue: z (256 px x 256 k) -> fp16 As, k perm16'd ----
    {
        const float* zb = z + (size_t)(m0 >> 10) * (KDIM * 1024) + (m0 & 1023);
        const int m = tid & 255, hh = tid >> 8;
        for (int g = 0; g < 8; g++) {
            __syncthreads();
            #pragma unroll
            for (int r = 0; r < 4; r++) {
                int q = tid + 512 * r;          // 0..2047 float4s
                int kk = q >> 6;                // 0..31
                int m4 = (q & 63) << 2;         // 0..252
                float4 v = *(const float4*)(zb + (size_t)(g * 32 + kk) * 1024 + m4);
                *(float4*)(stg + kk * 264 + m4) = v;
            }
            __syncthreads();
            #pragma unroll
            for (int pp = 0; pp < 8; pp++) {
                int p = hh * 8 + pp;            // 0..15 half2 pairs
                float f0 = stg[(2 * p) * 264 + m];
                float f1 = stg[(2 * p + 1) * 264 + m];
                int dest = ((p >> 3) & 1) * 16 + (p & 3) * 4 + ((p >> 2) & 1) * 2;
                __half2 h = __floats2half2_rn(f0, f1);
                *(__half2*)(As + m * 264 + g * 32 + dest) = h;
            }
        }
        #pragma unroll
        for (int r = 0; r < 2; r++) hn[tid + 512 * r] = g_hn_g[tid + 512 * r];
    }
    __syncthreads();

    // per-slot running best + 2 runner-ups within DELTA (4 slots: mf x cc-half)
    float best[4]; int bidx[4];
    float cv[4][2]; int ci[4][2];
    #pragma unroll
    for (int s = 0; s < 4; s++) {
        best[s] = -INFINITY; bidx[s] = 0;
        cv[s][0] = -INFINITY; cv[s][1] = -INFINITY;
        ci[s][0] = 0; ci[s][1] = 0;
    }

    for (int ct = 0; ct < 8; ct++) {
        float acc[2][8][4];
        #pragma unroll
        for (int mf = 0; mf < 2; mf++)
            #pragma unroll
            for (int nf = 0; nf < 8; nf++)
                #pragma unroll
                for (int cc = 0; cc < 4; cc++) acc[mf][nf][cc] = 0.0f;

        for (int kc = 0; kc < 8; kc++) {
            const int it = ct * 8 + kc;
            const int stage = it % 3;
            if (it == 63) { CP_WAIT0(); } else { CP_WAIT1(); }
            __syncthreads();
            if (it + 2 < 64) load_chunk(it + 2, (it + 2) % 3);

            const __half* B = Bsb + stage * B_STAGE_H;

            #pragma unroll
            for (int ks = 0; ks < 2; ks++) {
                uint32_t af[2][4];
                #pragma unroll
                for (int mf = 0; mf < 2; mf++) {
                    int r0 = mb + qr + mf * 16;
                    uint2 A1 = *(const uint2*)(As + r0 * 264 + kc * 32 + ks * 16 + qc * 4);
                    uint2 A2 = *(const uint2*)(As + (r0 + 8) * 264 + kc * 32 + ks * 16 + qc * 4);
                    af[mf][0] = A1.x; af[mf][2] = A1.y;
                    af[mf][1] = A2.x; af[mf][3] = A2.y;
                }
                #pragma unroll
                for (int nf = 0; nf < 8; nf++) {
                    int n = nb + nf * 8 + qr;
                    uint2 B2 = *(const uint2*)(B + n * 40 + ks * 16 + qc * 4);
                    mma16(acc[0][nf], af[0], B2.x, B2.y);
                    mma16(acc[1][nf], af[1], B2.x, B2.y);
                }
            }
        }

        // epilogue: subtract half-norm, fold into running argmax + candidate lists
        #pragma unroll
        for (int mf = 0; mf < 2; mf++)
            #pragma unroll
            for (int nf = 0; nf < 8; nf++)
                #pragma unroll
                for (int cc = 0; cc < 4; cc++) {
                    int col = nb + nf * 8 + 2 * qc + (cc & 1);
                    int code = ct * 128 + col;
                    float s = acc[mf][nf][cc] - hn[code];
                    int slot = mf * 2 + (cc >> 1);
                    if (s > best[slot]) {
                        float ov = best[slot]; int oi = bidx[slot];
                        if (cv[slot][0] <= cv[slot][1]) {
                            if (ov > cv[slot][0]) { cv[slot][0] = ov; ci[slot][0] = oi; }
                        } else {
                            if (ov > cv[slot][1]) { cv[slot][1] = ov; ci[slot][1] = oi; }
                        }
                        best[slot] = s; bidx[slot] = code;
                    } else if (s > best[slot] - DELTA) {
                        if (cv[slot][0] <= cv[slot][1]) {
                            if (s > cv[slot][0]) { cv[slot][0] = s; ci[slot][0] = code; }
                        } else {
                            if (s > cv[slot][1]) { cv[slot][1] = s; ci[slot][1] = code; }
                        }
                    }
                }
    }

    // per-pixel approx max: qc-lane reduce, then the 2 N-warps via smem
    #pragma unroll
    for (int s = 0; s < 4; s++) {
        float v = best[s];
        #pragma unroll
        for (int m = 1; m <= 2; m <<= 1) {
            float ov = __shfl_xor_sync(0xffffffffu, v, m);
            if (ov > v) v = ov;
        }
        if (qc == 0) {
            int row = mb + qr + (s >> 1) * 16 + (s & 1) * 8;
            redv[row * 2 + (wid & 1)] = v;
        }
    }
    __syncthreads();
    if (tid < 256) Vs[tid] = fmaxf(redv[tid * 2], redv[tid * 2 + 1]);
    __syncthreads();

    // emit candidates within DELTA of pixel approx max
    #pragma unroll
    for (int s = 0; s < 4; s++) {
        int row = mb + qr + (s >> 1) * 16 + (s & 1) * 8;
        float V = Vs[row];
        int p = m0 + row;
        if (best[s] > V - DELTA) {
            int pos = atomicAdd(&g_cnt[p], 1);
            if (pos < 8) g_cand[p * 8 + pos] = bidx[s];
        }
        if (cv[s][0] > V - DELTA) {
            int pos = atomicAdd(&g_cnt[p], 1);
            if (pos < 8) g_cand[p * 8 + pos] = ci[s][0];
        }
        if (cv[s][1] > V - DELTA) {
            int pos = atomicAdd(&g_cnt[p], 1);
            if (pos < 8) g_cand[p * 8 + pos] = ci[s][1];
        }
    }
}

// ---------------- kernel A2: exact fp32 rescoring (smem-staged z, coalesced) ----------------
__global__ void __launch_bounds__(256)
rescore_kernel(const float* __restrict__ z, const float* __restrict__ emb) {
    __shared__ float zs[32][257];
    const int t = threadIdx.x;
    const int w = t >> 5;
    const int l = t & 31;
    const int n0 = blockIdx.x * 32;
    const int b = n0 >> 10;
    const float* zb = z + (size_t)b * (KDIM * 1024) + (n0 & 1023);
    #pragma unroll
    for (int r = 0; r < 8; r++) {
        int q = t + 256 * r;            // 0..2047
        int kk = q >> 3;                // 0..255
        int h4 = (q & 7) << 2;          // 0..28
        float4 v = *(const float4*)(zb + (size_t)kk * 1024 + h4);
        zs[h4 + 0][kk] = v.x; zs[h4 + 1][kk] = v.y;
        zs[h4 + 2][kk] = v.z; zs[h4 + 3][kk] = v.w;
    }
    __syncthreads();
    #pragma unroll
    for (int px = 0; px < 4; px++) {
        int pix = w * 4 + px;
        int p = n0 + pix;
        int cnt = g_cnt[p];
        if (cnt > 8) cnt = 8;
        float bestv = -INFINITY;
        int besti = 0;
        for (int c = 0; c < cnt; c++) {
            int idx = g_cand[p * 8 + c];
            const float* e = emb + (size_t)idx * KDIM;
            float acc = 0.0f;
            #pragma unroll
            for (int j = 0; j < 8; j++)
                acc = fmaf(zs[pix][j * 32 + l], e[j * 32 + l], acc);
            #pragma unroll
            for (int m = 16; m >= 1; m >>= 1)
                acc += __shfl_xor_sync(0xffffffffu, acc, m);
            float s = acc - g_hn_g[idx];
            if (s > bestv || (s == bestv && idx < besti)) { bestv = s; besti = idx; }
        }
        if (l == 0) g_idx[p] = besti;
    }
}

// ---------------- kernel B1: gather z_q/z_q1 + squared-error partials + idx out ----------------
__global__ void __launch_bounds__(256)
gather_kernel(const float* __restrict__ z, const float* __restrict__ emb,
              float* __restrict__ out) {
    __shared__ float se[32][257];
    __shared__ int sidx[32];
    __shared__ float red[256];
    const int t = threadIdx.x;
    const int n0 = blockIdx.x * 32;
    if (t < 32) sidx[t] = g_idx[n0 + t];
    __syncthreads();
    if (t < 32) out[IDX_OFF + n0 + t] = (float)sidx[t];
    #pragma unroll
    for (int r = 0; r < 8; r++) {
        int q = t + 256 * r;
        int row = q >> 6;
        int c4 = (q & 63) << 2;
        float4 v = *(const float4*)(emb + (size_t)sidx[row] * KDIM + c4);
        se[row][c4 + 0] = v.x; se[row][c4 + 1] = v.y;
        se[row][c4 + 2] = v.z; se[row][c4 + 3] = v.w;
    }
    __syncthreads();
    const int hw = t & 31;
    const int cg = t >> 5;
    const int b = n0 >> 10;
    const int hwg = (n0 & 1023) + hw;
    const size_t zbase = (size_t)b * (KDIM * 1024) + hwg;
    float acc = 0.0f;
    #pragma unroll
    for (int ci2 = 0; ci2 < 32; ci2++) {
        int c = cg * 32 + ci2;
        float v = se[hw][c];
        size_t off = zbase + (size_t)c * 1024;
        float zv = z[off];
        float d = v - zv;
        acc += d * d;
        out[ZQ_OFF + off] = v;
        out[ZQ1_OFF + off] = v;
    }
    red[t] = acc;
    __syncthreads();
    #pragma unroll
    for (int s = 128; s > 0; s >>= 1) {
        if (t < s) red[t] += red[t + s];
        __syncthreads();
    }
    if (t == 0) g_partials[blockIdx.x] = red[0];
}

// ---------------- kernel B2: parallel histogram ----------------
__global__ void hist_kernel() {
    __shared__ int h[NE];
    const int t = threadIdx.x;       // 32 blocks x 256 threads
    #pragma unroll
    for (int r = 0; r < 4; r++) h[t + 256 * r] = 0;
    __syncthreads();
    const int base = blockIdx.x * 1024;
    #pragma unroll
    for (int r = 0; r < 4; r++) {
        int id = g_idx[base + t + 256 * r];
        atomicAdd(&h[id], 1);
    }
    __syncthreads();
    #pragma unroll
    for (int r = 0; r < 4; r++) {
        int v = h[t + 256 * r];
        if (v) atomicAdd(&g_hist[t + 256 * r], v);
    }
}

// ---------------- kernel B3: loss + perplexity ----------------
__global__ void finalize_kernel(float* __restrict__ out) {
    __shared__ float red[1024];
    const int t = threadIdx.x;       // 1024 threads, 1 block
    red[t] = g_partials[t];
    __syncthreads();
    #pragma unroll
    for (int s = 512; s > 0; s >>= 1) {
        if (t < s) red[t] += red[t + s];
        __syncthreads();
    }
    float loss = red[0] * (1.0f + BETA) / 8388608.0f;
    __syncthreads();
    float p = (float)g_hist[t] / (float)NPIX;
    red[t] = p * logf(p + EPS_P);
    __syncthreads();
    #pragma unroll
    for (int s = 512; s > 0; s >>= 1) {
        if (t < s) red[t] += red[t + s];
        __syncthreads();
    }
    if (t == 0) {
        out[0] = loss;
        out[PERP_OFF] = expf(-red[0]);
    }
}

// ---------------- launch ----------------
extern "C" void kernel_launch(void* const* d_in, const int* in_sizes, int n_in,
                              void* d_out, int out_size) {
    const float* z   = (const float*)d_in[0];
    const float* emb = (const float*)d_in[1];
    float* out = (float*)d_out;

    split_kernel<<<NE, 256>>>(emb);
    dummy1_kernel<<<1, 32>>>();      // ncu alignment: argmin is launch #4
    dummy2_kernel<<<1, 32>>>();

    cudaFuncSetAttribute(argmin_mma_kernel,
                         cudaFuncAttributeMaxDynamicSharedMemorySize, SMB_TOTAL);
    argmin_mma_kernel<<<NPIX / 256, 512, SMB_TOTAL>>>(z);

    rescore_kernel<<<NPIX / 32, 256>>>(z, emb);
    gather_kernel<<<NPIX / 32, 256>>>(z, emb, out);
    hist_kernel<<<32, 256>>>();
    finalize_kernel<<<1, 1024>>>(out);
}